// round 14
// baseline (speedup 1.0000x reference)
#include <cuda_runtime.h>
#include <cuda_bf16.h>
#include <math.h>
#include <stdint.h>

// Problem constants
#define BB 16
#define LL 50
#define PP 49
#define TT 20
#define DD 512
#define HH 8
#define DH 64
#define DFF 2048
#define BL (BB*LL)              // 800
#define NROW_IMG (BL*TT)        // 16000
#define NROW_TIT (BL*PP)        // 39200
#define NROW_ALL (NROW_IMG + NROW_TIT)   // 55200
#define YT64_IMG (NROW_IMG / 64)         // 250 (exact)
#define NEGV (-1000000000.0f)
#define LN_EPS 1e-6f

// ---------------------------------------------------------------------------
// Scratch (device globals) — img rows first, tit rows after (contiguous)
// ---------------------------------------------------------------------------
__device__ __align__(16) __nv_bfloat16 g_hid_h [(size_t)NROW_ALL * DD];
__device__ __align__(16) __nv_bfloat16 g_hid_l [(size_t)NROW_ALL * DD];
__device__ __align__(16) float         g_hidp_f[(size_t)NROW_ALL * DD];
__device__ __align__(16) __nv_bfloat16 g_hidp_h[(size_t)NROW_ALL * DD];
__device__ __align__(16) __nv_bfloat16 g_hidp_l[(size_t)NROW_ALL * DD];
__device__ __align__(16) __nv_bfloat16 g_ffh_h [(size_t)NROW_ALL * DFF];
__device__ __align__(16) __nv_bfloat16 g_ffh_l [(size_t)NROW_ALL * DFF];
__device__ __align__(16) float         g_ff2   [(size_t)NROW_ALL * DD];
__device__ __align__(16) __nv_bfloat16 g_wp_h [(size_t)DD * DD];
__device__ __align__(16) __nv_bfloat16 g_wp_l [(size_t)DD * DD];
__device__ __align__(16) __nv_bfloat16 g_w1i_h[(size_t)DFF * DD];
__device__ __align__(16) __nv_bfloat16 g_w1i_l[(size_t)DFF * DD];
__device__ __align__(16) __nv_bfloat16 g_w1t_h[(size_t)DFF * DD];
__device__ __align__(16) __nv_bfloat16 g_w1t_l[(size_t)DFF * DD];
__device__ __align__(16) __nv_bfloat16 g_w2i_h[(size_t)DD * DFF];
__device__ __align__(16) __nv_bfloat16 g_w2i_l[(size_t)DD * DFF];
__device__ __align__(16) __nv_bfloat16 g_w2t_h[(size_t)DD * DFF];
__device__ __align__(16) __nv_bfloat16 g_w2t_l[(size_t)DD * DFF];

// ---------------------------------------------------------------------------
// Helpers
// ---------------------------------------------------------------------------
__device__ __forceinline__ uint32_t smem_u32(const void* p) {
    uint32_t a;
    asm("{ .reg .u64 t; cvta.to.shared.u64 t, %1; cvt.u32.u64 %0, t; }" : "=r"(a) : "l"(p));
    return a;
}
__device__ __forceinline__ void cp16(uint32_t dst, const void* src, int sz) {
    asm volatile("cp.async.cg.shared.global [%0], [%1], 16, %2;"
                 :: "r"(dst), "l"(src), "r"(sz));
}
__device__ __forceinline__ void cp_commit() { asm volatile("cp.async.commit_group;" ::: "memory"); }
__device__ __forceinline__ void cp_wait1()  { asm volatile("cp.async.wait_group 1;" ::: "memory"); }
__device__ __forceinline__ void cp_wait0()  { asm volatile("cp.async.wait_group 0;" ::: "memory"); }

__device__ __forceinline__ void ldsm4(uint32_t* r, uint32_t addr) {
    asm volatile("ldmatrix.sync.aligned.m8n8.x4.shared.b16 {%0,%1,%2,%3}, [%4];"
                 : "=r"(r[0]), "=r"(r[1]), "=r"(r[2]), "=r"(r[3]) : "r"(addr));
}
__device__ __forceinline__ void mma16816(float* c, const uint32_t* a, const uint32_t* b) {
    asm volatile(
        "mma.sync.aligned.m16n8k16.row.col.f32.bf16.bf16.f32 "
        "{%0,%1,%2,%3}, {%4,%5,%6,%7}, {%8,%9}, {%0,%1,%2,%3};"
        : "+f"(c[0]), "+f"(c[1]), "+f"(c[2]), "+f"(c[3])
        : "r"(a[0]), "r"(a[1]), "r"(a[2]), "r"(a[3]), "r"(b[0]), "r"(b[1]));
}

__device__ __forceinline__ float gelu_fast(float x) {
    float y = 0.7978845608028654f * (x + 0.044715f * x * x * x);
    float e = __expf(2.f * y);
    return x - __fdividef(x, 1.f + e);
}
__device__ __forceinline__ void split_f32(float v, __nv_bfloat16& h, __nv_bfloat16& l) {
    h = __float2bfloat16(v);
    l = __float2bfloat16(v - __bfloat162float(h));
}

// Swizzled smem address: rows of 32 bf16 (64B), two rows packed per 128B line,
// 16B slot = ((row&1)*4 | k/8) ^ (lrow&7). Conflict-free for ldmatrix groups.
__device__ __forceinline__ uint32_t swaddr(uint32_t row, uint32_t ks) {
    uint32_t lrow = row >> 1;
    return lrow * 128u + (((((row & 1u) << 2) | ks) ^ (lrow & 7u)) << 4);
}

// ---------------------------------------------------------------------------
// Merged weight split kernel
// ---------------------------------------------------------------------------
#define SEG0 (DD*DD)
#define SEG1 (SEG0 + DFF*DD)
#define SEG2 (SEG1 + DFF*DD)
#define SEG3 (SEG2 + DD*DFF)
#define SEG4 (SEG3 + DD*DFF)

__device__ __forceinline__ void split4(const float* src, __nv_bfloat16* hi,
                                       __nv_bfloat16* lo, int i) {
    float4 v = *(const float4*)(src + i);
    __nv_bfloat16 h0, h1, h2, h3, l0, l1, l2, l3;
    split_f32(v.x, h0, l0); split_f32(v.y, h1, l1);
    split_f32(v.z, h2, l2); split_f32(v.w, h3, l3);
    __nv_bfloat162 hp0 = __halves2bfloat162(h0, h1);
    __nv_bfloat162 hp1 = __halves2bfloat162(h2, h3);
    __nv_bfloat162 lp0 = __halves2bfloat162(l0, l1);
    __nv_bfloat162 lp1 = __halves2bfloat162(l2, l3);
    *(uint2*)(hi + i) = make_uint2(*(uint32_t*)&hp0, *(uint32_t*)&hp1);
    *(uint2*)(lo + i) = make_uint2(*(uint32_t*)&lp0, *(uint32_t*)&lp1);
}

__global__ void __launch_bounds__(256) split_all_kernel(
    const float* __restrict__ wp, const float* __restrict__ w1i,
    const float* __restrict__ w1t, const float* __restrict__ w2i,
    const float* __restrict__ w2t)
{
    int g = (blockIdx.x * 256 + threadIdx.x) * 4;
    if (g >= SEG4) return;
    if (g < SEG0)      split4(wp,  g_wp_h,  g_wp_l,  g);
    else if (g < SEG1) split4(w1i, g_w1i_h, g_w1i_l, g - SEG0);
    else if (g < SEG2) split4(w1t, g_w1t_h, g_w1t_l, g - SEG1);
    else if (g < SEG3) split4(w2i, g_w2i_h, g_w2i_l, g - SEG2);
    else               split4(w2t, g_w2t_h, g_w2t_l, g - SEG3);
}

// ---------------------------------------------------------------------------
// Fused attention (emits bf16 hi/lo into merged row layout)
// ---------------------------------------------------------------------------
__global__ void __launch_bounds__(256) attn_kernel(
    const float* __restrict__ img, const float* __restrict__ title,
    const int* __restrict__ mask,
    const float* __restrict__ s_img, const float* __restrict__ s_tit)
{
    int blk = blockIdx.x;
    int h   = blk % HH;
    int bl  = blk / HH;

    const float* imgp = img   + (size_t)bl * PP * DD + h * DH;
    const float* titp = title + (size_t)bl * TT * DD + h * DH;
    const int*   mp   = mask  + (size_t)bl * TT;

    __shared__ float sI[PP * DH];
    __shared__ float sT[TT * DH];
    __shared__ float sRaw[PP * TT];
    __shared__ float sPi [PP * TT];
    __shared__ float sPt [TT * PP];
    __shared__ int   sM[TT];

    int tid = threadIdx.x;
    for (int i = tid; i < PP * DH; i += 256) {
        int p = i >> 6, d = i & 63;
        sI[i] = imgp[(size_t)p * DD + d];
    }
    for (int i = tid; i < TT * DH; i += 256) {
        int t = i >> 6, d = i & 63;
        sT[i] = titp[(size_t)t * DD + d];
    }
    if (tid < TT) sM[tid] = mp[tid];
    __syncthreads();

    for (int i = tid; i < PP * TT; i += 256) {
        int p = i / TT, t = i % TT;
        const float* ip = &sI[p * DH];
        const float* tp = &sT[t * DH];
        float acc = 0.f;
        #pragma unroll
        for (int d = 0; d < DH; d++) acc += ip[d] * tp[d];
        sRaw[i] = acc * 0.125f;
    }
    __syncthreads();

    if (tid < PP) {
        int p = tid;
        float sc = s_img[h * PP + p];
        float mx = -1e30f;
        for (int t = 0; t < TT; t++) {
            float x = (sM[t] == 0) ? NEGV : sRaw[p * TT + t] * sc;
            sPi[p * TT + t] = x;
            mx = fmaxf(mx, x);
        }
        float sum = 0.f;
        for (int t = 0; t < TT; t++) {
            float e = __expf(sPi[p * TT + t] - mx);
            sPi[p * TT + t] = e;
            sum += e;
        }
        float inv = 1.f / sum;
        for (int t = 0; t < TT; t++) sPi[p * TT + t] *= inv;
    }
    if (tid >= 64 && tid < 64 + TT) {
        int t = tid - 64;
        float sc = s_tit[h * TT + t];
        bool m0 = (sM[t] == 0);
        float mx = -1e30f;
        for (int p = 0; p < PP; p++) {
            float x = m0 ? NEGV : sRaw[p * TT + t] * sc;
            sPt[t * PP + p] = x;
            mx = fmaxf(mx, x);
        }
        float sum = 0.f;
        for (int p = 0; p < PP; p++) {
            float e = __expf(sPt[t * PP + p] - mx);
            sPt[t * PP + p] = e;
            sum += e;
        }
        float inv = 1.f / sum;
        for (int p = 0; p < PP; p++) sPt[t * PP + p] *= inv;
    }
    __syncthreads();

    for (int i = tid; i < PP * DH; i += 256) {
        int p = i >> 6, d = i & 63;
        float acc = 0.f;
        #pragma unroll
        for (int t = 0; t < TT; t++) acc += sPi[p * TT + t] * sT[t * DH + d];
        size_t idx = ((size_t)(NROW_IMG + bl * PP + p)) * DD + h * DH + d;
        __nv_bfloat16 hh, ll;
        split_f32(acc, hh, ll);
        g_hid_h[idx] = hh;
        g_hid_l[idx] = ll;
    }
    for (int i = tid; i < TT * DH; i += 256) {
        int t = i >> 6, d = i & 63;
        float acc = 0.f;
        #pragma unroll
        for (int p = 0; p < PP; p++) acc += sPt[t * PP + p] * sI[p * DH + d];
        size_t idx = ((size_t)(bl * TT + t)) * DD + h * DH + d;
        __nv_bfloat16 hh, ll;
        split_f32(acc, hh, ll);
        g_hid_h[idx] = hh;
        g_hid_l[idx] = ll;
    }
}

// ---------------------------------------------------------------------------
// mma.sync GEMM (bf16x3): C[M,N] = act(A @ W^T + bias)
// Block tile 64m x 64n, 128 threads / 4 warps (2m x 2n, 32x32 warp tile),
// KC=32, 3-stage cp.async, swizzled smem -> 4 CTAs/SM.
// Strength-reduced mainloop: all cp.async pointers and ldmatrix offsets
// precomputed per-thread; pointers advance by +64B per chunk.
// ---------------------------------------------------------------------------
#define KC 32
#define TEN_A 4096u                       // 64 rows x 64B
#define TEN_W 4096u                       // 64 rows x 64B
#define STG_BYTES (2*TEN_A + 2*TEN_W)     // 16384
#define OFF_AL TEN_A
#define OFF_WH (2*TEN_A)
#define OFF_WL (2*TEN_A + TEN_W)
#define NSTAGE 3
#define SMEM_GEMM (NSTAGE * STG_BYTES)    // 49152

__global__ void __launch_bounds__(128, 4) gemm_mma(
    const __nv_bfloat16* __restrict__ Ah, const __nv_bfloat16* __restrict__ Al,
    const __nv_bfloat16* __restrict__ WhA, const __nv_bfloat16* __restrict__ WlA,
    const __nv_bfloat16* __restrict__ WhB, const __nv_bfloat16* __restrict__ WlB,
    const float* __restrict__ biasA, const float* __restrict__ biasB,
    float* __restrict__ Cf, __nv_bfloat16* __restrict__ Chi, __nv_bfloat16* __restrict__ Clo,
    int M, int N, int K, int act, int ysplit)
{
    extern __shared__ __align__(128) char smem[];
    uint32_t sb = smem_u32(smem);
    int tid  = threadIdx.x;
    int wid  = tid >> 5, lane = tid & 31;
    int m0   = blockIdx.y * 64;
    int n0   = blockIdx.x * 64;
    int wm   = (wid & 1) * 32;            // 2 m-warps
    int wn   = (wid >> 1) * 32;           // 2 n-warps

    bool regA = ((int)blockIdx.y < ysplit);
    const __nv_bfloat16* Wh = regA ? WhA : WhB;
    const __nv_bfloat16* Wl = regA ? WlA : WlB;
    const float*       bias = regA ? biasA : biasB;

    // ---- precomputed cp.async state (per-thread constants + running ptrs) ----
    int rA0 = tid >> 2,               ksA0 = tid & 3;
    int rA1 = (tid + 128) >> 2,       ksA1 = tid & 3;   // (tid+128)&3 == tid&3
    uint32_t dA0 = swaddr((uint32_t)rA0, (uint32_t)ksA0);
    uint32_t dA1 = swaddr((uint32_t)rA1, (uint32_t)ksA1);
    int okA0 = (m0 + rA0 < M), okA1 = (m0 + rA1 < M);
    int szA0 = okA0 ? 16 : 0,  szA1 = okA1 ? 16 : 0;
    const char* pAh0 = (const char*)(Ah + (size_t)(okA0 ? m0 + rA0 : 0) * K + ksA0 * 8);
    const char* pAl0 = (const char*)(Al + (size_t)(okA0 ? m0 + rA0 : 0) * K + ksA0 * 8);
    const char* pAh1 = (const char*)(Ah + (size_t)(okA1 ? m0 + rA1 : 0) * K + ksA1 * 8);
    const char* pAl1 = (const char*)(Al + (size_t)(okA1 ? m0 + rA1 : 0) * K + ksA1 * 8);
    const char* pWh0 = (const char*)(Wh + (size_t)(n0 + rA0) * K + ksA0 * 8);
    const char* pWl0 = (const char*)(Wl + (size_t)(n0 + rA0) * K + ksA0 * 8);
    const char* pWh1 = (const char*)(Wh + (size_t)(n0 + rA1) * K + ksA1 * 8);
    const char* pWl1 = (const char*)(Wl + (size_t)(n0 + rA1) * K + ksA1 * 8);

    // ---- precomputed ldmatrix stage-relative offsets ----
    uint32_t a_row = (uint32_t)(lane & 15);
    uint32_t a_kof = (uint32_t)((lane >> 4) << 3);
    uint32_t b_r8  = (uint32_t)(lane & 7);
    uint32_t b_kof = (uint32_t)(((lane >> 3) & 1) << 3);
    uint32_t b_pr  = (uint32_t)(lane >> 4);
    uint32_t oA[2][2], oB[2][2];   // [kk16][mt/np] -> hi-tensor offsets
    #pragma unroll
    for (int k2 = 0; k2 < 2; k2++) {
        #pragma unroll
        for (int mt = 0; mt < 2; mt++)
            oA[k2][mt] = swaddr((uint32_t)(wm + mt * 16) + a_row,
                                ((uint32_t)(k2 * 16) + a_kof) >> 3);
        #pragma unroll
        for (int np = 0; np < 2; np++)
            oB[k2][np] = OFF_WH + swaddr((uint32_t)wn + ((uint32_t)np * 2 + b_pr) * 8 + b_r8,
                                         ((uint32_t)(k2 * 16) + b_kof) >> 3);
    }

    float acc[2][4][4];
    #pragma unroll
    for (int a = 0; a < 2; a++)
        #pragma unroll
        for (int b = 0; b < 4; b++)
            #pragma unroll
            for (int c = 0; c < 4; c++) acc[a][b][c] = 0.f;

    int nk = K / KC;

    // chunk loader: 8 cp.async from running pointers, then advance by 64B
    #define LOAD_CHUNK(ST) do {                                   \
        cp16((ST) + dA0,          pAh0, szA0);                    \
        cp16((ST) + OFF_AL + dA0, pAl0, szA0);                    \
        cp16((ST) + dA1,          pAh1, szA1);                    \
        cp16((ST) + OFF_AL + dA1, pAl1, szA1);                    \
        cp16((ST) + OFF_WH + dA0, pWh0, 16);                      \
        cp16((ST) + OFF_WL + dA0, pWl0, 16);                      \
        cp16((ST) + OFF_WH + dA1, pWh1, 16);                      \
        cp16((ST) + OFF_WL + dA1, pWl1, 16);                      \
        pAh0 += 64; pAl0 += 64; pAh1 += 64; pAl1 += 64;           \
        pWh0 += 64; pWl0 += 64; pWh1 += 64; pWl1 += 64;           \
        cp_commit();                                              \
    } while (0)

    LOAD_CHUNK(sb);
    LOAD_CHUNK(sb + STG_BYTES);

    for (int it = 0; it < nk; it++) {
        if (it < nk - 1) cp_wait1(); else cp_wait0();
        __syncthreads();
        if (it + 2 < nk) {
            LOAD_CHUNK(sb + (uint32_t)((it + 2) % 3) * STG_BYTES);
        }
        uint32_t st = sb + (uint32_t)(it % 3) * STG_BYTES;

        #pragma unroll
        for (int k2 = 0; k2 < 2; k2++) {
            uint32_t ah[2][4], al[2][4], bh[4][2], blr[4][2];
            #pragma unroll
            for (int mt = 0; mt < 2; mt++) {
                uint32_t ad = st + oA[k2][mt];
                ldsm4(ah[mt], ad);
                ldsm4(al[mt], ad + OFF_AL);
            }
            #pragma unroll
            for (int np = 0; np < 2; np++) {
                uint32_t bd = st + oB[k2][np];
                uint32_t t0[4], t1[4];
                ldsm4(t0, bd);
                ldsm4(t1, bd + TEN_W);
                bh [np*2][0]   = t0[0]; bh [np*2][1]   = t0[1];
                bh [np*2+1][0] = t0[2]; bh [np*2+1][1] = t0[3];
                blr[np*2][0]   = t1[0]; blr[np*2][1]   = t1[1];
                blr[np*2+1][0] = t1[2]; blr[np*2+1][1] = t1[3];
            }
            #pragma unroll
            for (int mt = 0; mt < 2; mt++)
                #pragma unroll
                for (int nt = 0; nt < 4; nt++) {
                    mma16816(acc[mt][nt], ah[mt], bh[nt]);
                    mma16816(acc[mt][nt], ah[mt], blr[nt]);
                    mma16816(acc[mt][nt], al[mt], bh[nt]);
                }
        }
    }
    #undef LOAD_CHUNK

    // epilogue
    int gr = lane >> 2;
    int gc = (lane & 3) * 2;
    #pragma unroll
    for (int mt = 0; mt < 2; mt++) {
        int m_lo = m0 + wm + mt * 16 + gr;
        int m_hi = m_lo + 8;
        #pragma unroll
        for (int nt = 0; nt < 4; nt++) {
            int n = n0 + wn + nt * 8 + gc;
            float2 bv = *(const float2*)&bias[n];
            float v0 = acc[mt][nt][0] + bv.x;
            float v1 = acc[mt][nt][1] + bv.y;
            float v2 = acc[mt][nt][2] + bv.x;
            float v3 = acc[mt][nt][3] + bv.y;
            if (act) { v0 = gelu_fast(v0); v1 = gelu_fast(v1);
                       v2 = gelu_fast(v2); v3 = gelu_fast(v3); }
            if (m_lo < M) {
                size_t o = (size_t)m_lo * N + n;
                if (Cf) *(float2*)&Cf[o] = make_float2(v0, v1);
                if (Chi) {
                    __nv_bfloat16 h0, l0, h1, l1;
                    split_f32(v0, h0, l0); split_f32(v1, h1, l1);
                    __nv_bfloat162 hp = __halves2bfloat162(h0, h1);
                    __nv_bfloat162 lp = __halves2bfloat162(l0, l1);
                    *(uint32_t*)&Chi[o] = *(uint32_t*)&hp;
                    *(uint32_t*)&Clo[o] = *(uint32_t*)&lp;
                }
            }
            if (m_hi < M) {
                size_t o = (size_t)m_hi * N + n;
                if (Cf) *(float2*)&Cf[o] = make_float2(v2, v3);
                if (Chi) {
                    __nv_bfloat16 h0, l0, h1, l1;
                    split_f32(v2, h0, l0); split_f32(v3, h1, l1);
                    __nv_bfloat162 hp = __halves2bfloat162(h0, h1);
                    __nv_bfloat162 lp = __halves2bfloat162(l0, l1);
                    *(uint32_t*)&Chi[o] = *(uint32_t*)&hp;
                    *(uint32_t*)&Clo[o] = *(uint32_t*)&lp;
                }
            }
        }
    }
}

// ---------------------------------------------------------------------------
// out = R + a * (Y - mean) / (std + eps) + b   per row of 512, ddof=1
// ---------------------------------------------------------------------------
__global__ void __launch_bounds__(128) ln_res_kernel(
    const float* __restrict__ Y, const float* __restrict__ R,
    const float* __restrict__ ga_i, const float* __restrict__ gb_i,
    const float* __restrict__ ga_t, const float* __restrict__ gb_t,
    float* __restrict__ O)
{
    __shared__ float sbuf[4];
    int row = blockIdx.x;
    const float* ga = (row < NROW_IMG) ? ga_i : ga_t;
    const float* gb = (row < NROW_IMG) ? gb_i : gb_t;
    size_t base = (size_t)row * DD;
    int tid = threadIdx.x;

    float x[4];
    #pragma unroll
    for (int i = 0; i < 4; i++) x[i] = Y[base + tid + i * 128];

    float s = x[0] + x[1] + x[2] + x[3];
    #pragma unroll
    for (int o = 16; o > 0; o >>= 1) s += __shfl_xor_sync(0xffffffffu, s, o);
    if ((tid & 31) == 0) sbuf[tid >> 5] = s;
    __syncthreads();
    float mean = (sbuf[0] + sbuf[1] + sbuf[2] + sbuf[3]) * (1.f / 512.f);
    __syncthreads();

    float q = 0.f;
    #pragma unroll
    for (int i = 0; i < 4; i++) { float d = x[i] - mean; q += d * d; }
    #pragma unroll
    for (int o = 16; o > 0; o >>= 1) q += __shfl_xor_sync(0xffffffffu, q, o);
    if ((tid & 31) == 0) sbuf[tid >> 5] = q;
    __syncthreads();
    float var = (sbuf[0] + sbuf[1] + sbuf[2] + sbuf[3]) * (1.f / 511.f);
    float inv = 1.f / (sqrtf(var) + LN_EPS);

    #pragma unroll
    for (int i = 0; i < 4; i++) {
        int n = tid + i * 128;
        O[base + n] = R[base + n] + ga[n] * (x[i] - mean) * inv + gb[n];
    }
}

// ---------------------------------------------------------------------------
extern "C" void kernel_launch(void* const* d_in, const int* in_sizes, int n_in,
                              void* d_out, int out_size)
{
    const float* img         = (const float*)d_in[0];
    const float* title       = (const float*)d_in[1];
    const int*   mask        = (const int*)  d_in[2];
    const float* scale_img   = (const float*)d_in[3];
    const float* scale_title = (const float*)d_in[4];
    const float* w_proj      = (const float*)d_in[5];
    const float* b_proj      = (const float*)d_in[6];
    const float* w1_img      = (const float*)d_in[7];
    const float* b1_img      = (const float*)d_in[8];
    const float* w2_img      = (const float*)d_in[9];
    const float* b2_img      = (const float*)d_in[10];
    const float* w1_tit      = (const float*)d_in[11];
    const float* b1_tit      = (const float*)d_in[12];
    const float* w2_tit      = (const float*)d_in[13];
    const float* b2_tit      = (const float*)d_in[14];
    const float* ln_a_img    = (const float*)d_in[15];
    const float* ln_b_img    = (const float*)d_in[16];
    const float* ln_a_tit    = (const float*)d_in[17];
    const float* ln_b_tit    = (const float*)d_in[18];

    float* out = (float*)d_out;

    cudaFuncSetAttribute(gemm_mma, cudaFuncAttributeMaxDynamicSharedMemorySize, SMEM_GEMM);

    __nv_bfloat16 *hid_h, *hid_l, *hidp_h, *hidp_l, *ffh_h, *ffh_l;
    float *hidp_f, *ff2;
    __nv_bfloat16 *wp_h, *wp_l, *w1i_h, *w1i_l, *w1t_h, *w1t_l, *w2i_h, *w2i_l, *w2t_h, *w2t_l;

    cudaGetSymbolAddress((void**)&hid_h,  g_hid_h);
    cudaGetSymbolAddress((void**)&hid_l,  g_hid_l);
    cudaGetSymbolAddress((void**)&hidp_f, g_hidp_f);
    cudaGetSymbolAddress((void**)&hidp_h, g_hidp_h);
    cudaGetSymbolAddress((void**)&hidp_l, g_hidp_l);
    cudaGetSymbolAddress((void**)&ffh_h,  g_ffh_h);
    cudaGetSymbolAddress((void**)&ffh_l,  g_ffh_l);
    cudaGetSymbolAddress((void**)&ff2,    g_ff2);
    cudaGetSymbolAddress((void**)&wp_h,  g_wp_h);  cudaGetSymbolAddress((void**)&wp_l,  g_wp_l);
    cudaGetSymbolAddress((void**)&w1i_h, g_w1i_h); cudaGetSymbolAddress((void**)&w1i_l, g_w1i_l);
    cudaGetSymbolAddress((void**)&w1t_h, g_w1t_h); cudaGetSymbolAddress((void**)&w1t_l, g_w1t_l);
    cudaGetSymbolAddress((void**)&w2i_h, g_w2i_h); cudaGetSymbolAddress((void**)&w2i_l, g_w2i_l);
    cudaGetSymbolAddress((void**)&w2t_h, g_w2t_h); cudaGetSymbolAddress((void**)&w2t_l, g_w2t_l);

    int ty = (NROW_ALL + 63) / 64;   // 863

    // launch 0: merged weight split
    split_all_kernel<<<(SEG4 / 4 + 255) / 256, 256>>>(w_proj, w1_img, w1_tit, w2_img, w2_tit);

    // launch 1: attention
    attn_kernel<<<BL * HH, 256>>>(img, title, mask, scale_img, scale_title);

    // launch 2: shared projection
    gemm_mma<<<dim3(DD/64, ty), 128, SMEM_GEMM>>>(
        hid_h, hid_l, wp_h, wp_l, wp_h, wp_l, b_proj, b_proj,
        hidp_f, hidp_h, hidp_l, NROW_ALL, DD, DD, 0, ty);

    // launch 3 (ncu capture slot): FFN1 + gelu
    gemm_mma<<<dim3(DFF/64, ty), 128, SMEM_GEMM>>>(
        hidp_h, hidp_l, w1i_h, w1i_l, w1t_h, w1t_l, b1_img, b1_tit,
        (float*)0, ffh_h, ffh_l, NROW_ALL, DFF, DD, 1, YT64_IMG);

    // launch 4: FFN2
    gemm_mma<<<dim3(DD/64, ty), 128, SMEM_GEMM>>>(
        ffh_h, ffh_l, w2i_h, w2i_l, w2t_h, w2t_l, b2_img, b2_tit,
        ff2, (__nv_bfloat16*)0, (__nv_bfloat16*)0, NROW_ALL, DD, DFF, 0, YT64_IMG);

    // launch 5: LayerNorm + residual
    ln_res_kernel<<<NROW_ALL, 128>>>(ff2, hidp_f, ln_a_img, ln_b_img, ln_a_tit, ln_b_tit, out);
}

// round 15
// speedup vs baseline: 1.4841x; 1.4841x over previous
#include <cuda_runtime.h>
#include <cuda_fp16.h>
#include <math.h>
#include <stdint.h>

// Problem constants
#define BB 16
#define LL 50
#define PP 49
#define TT 20
#define DD 512
#define HH 8
#define DH 64
#define DFF 2048
#define BL (BB*LL)              // 800
#define NROW_IMG (BL*TT)        // 16000
#define NROW_TIT (BL*PP)        // 39200
#define NROW_ALL (NROW_IMG + NROW_TIT)   // 55200
#define YT64_IMG (NROW_IMG / 64)         // 250 (exact)
#define NEGV (-1000000000.0f)
#define LN_EPS 1e-6f

// ---------------------------------------------------------------------------
// Scratch (device globals) — img rows first, tit rows after (contiguous)
// ---------------------------------------------------------------------------
__device__ __align__(16) __half g_hid [(size_t)NROW_ALL * DD];
__device__ __align__(16) float  g_hidp_f[(size_t)NROW_ALL * DD];
__device__ __align__(16) __half g_hidp[(size_t)NROW_ALL * DD];
__device__ __align__(16) __half g_ffh [(size_t)NROW_ALL * DFF];
__device__ __align__(16) float  g_ff2 [(size_t)NROW_ALL * DD];
__device__ __align__(16) __half g_wp  [(size_t)DD * DD];
__device__ __align__(16) __half g_w1i [(size_t)DFF * DD];
__device__ __align__(16) __half g_w1t [(size_t)DFF * DD];
__device__ __align__(16) __half g_w2i [(size_t)DD * DFF];
__device__ __align__(16) __half g_w2t [(size_t)DD * DFF];

// ---------------------------------------------------------------------------
// Helpers
// ---------------------------------------------------------------------------
__device__ __forceinline__ uint32_t smem_u32(const void* p) {
    uint32_t a;
    asm("{ .reg .u64 t; cvta.to.shared.u64 t, %1; cvt.u32.u64 %0, t; }" : "=r"(a) : "l"(p));
    return a;
}
__device__ __forceinline__ void cp16(uint32_t dst, const void* src, int sz) {
    asm volatile("cp.async.cg.shared.global [%0], [%1], 16, %2;"
                 :: "r"(dst), "l"(src), "r"(sz));
}
__device__ __forceinline__ void cp_commit() { asm volatile("cp.async.commit_group;" ::: "memory"); }
__device__ __forceinline__ void cp_wait2()  { asm volatile("cp.async.wait_group 2;" ::: "memory"); }
__device__ __forceinline__ void cp_wait1()  { asm volatile("cp.async.wait_group 1;" ::: "memory"); }
__device__ __forceinline__ void cp_wait0()  { asm volatile("cp.async.wait_group 0;" ::: "memory"); }

__device__ __forceinline__ void ldsm4(uint32_t* r, uint32_t addr) {
    asm volatile("ldmatrix.sync.aligned.m8n8.x4.shared.b16 {%0,%1,%2,%3}, [%4];"
                 : "=r"(r[0]), "=r"(r[1]), "=r"(r[2]), "=r"(r[3]) : "r"(addr));
}
// fp16 inputs, fp32 accumulate
__device__ __forceinline__ void mma16816(float* c, const uint32_t* a, const uint32_t* b) {
    asm volatile(
        "mma.sync.aligned.m16n8k16.row.col.f32.f16.f16.f32 "
        "{%0,%1,%2,%3}, {%4,%5,%6,%7}, {%8,%9}, {%0,%1,%2,%3};"
        : "+f"(c[0]), "+f"(c[1]), "+f"(c[2]), "+f"(c[3])
        : "r"(a[0]), "r"(a[1]), "r"(a[2]), "r"(a[3]), "r"(b[0]), "r"(b[1]));
}

__device__ __forceinline__ float gelu_fast(float x) {
    float y = 0.7978845608028654f * (x + 0.044715f * x * x * x);
    float e = __expf(2.f * y);
    return x - __fdividef(x, 1.f + e);
}

// Swizzled smem address: rows of 64B, two rows packed per 128B line,
// 16B slot = ((row&1)*4 | ks) ^ (lrow&7). Conflict-free for ldmatrix groups.
__device__ __forceinline__ uint32_t swaddr(uint32_t row, uint32_t ks) {
    uint32_t lrow = row >> 1;
    return lrow * 128u + (((((row & 1u) << 2) | ks) ^ (lrow & 7u)) << 4);
}

// ---------------------------------------------------------------------------
// Merged weight convert kernel (f32 -> f16)
// ---------------------------------------------------------------------------
#define SEG0 (DD*DD)
#define SEG1 (SEG0 + DFF*DD)
#define SEG2 (SEG1 + DFF*DD)
#define SEG3 (SEG2 + DD*DFF)
#define SEG4 (SEG3 + DD*DFF)

__device__ __forceinline__ void conv4(const float* src, __half* dst, int i) {
    float4 v = *(const float4*)(src + i);
    __half2 p0 = __floats2half2_rn(v.x, v.y);
    __half2 p1 = __floats2half2_rn(v.z, v.w);
    *(uint2*)(dst + i) = make_uint2(*(uint32_t*)&p0, *(uint32_t*)&p1);
}

__global__ void __launch_bounds__(256) conv_all_kernel(
    const float* __restrict__ wp, const float* __restrict__ w1i,
    const float* __restrict__ w1t, const float* __restrict__ w2i,
    const float* __restrict__ w2t)
{
    int g = (blockIdx.x * 256 + threadIdx.x) * 4;
    if (g >= SEG4) return;
    if (g < SEG0)      conv4(wp,  g_wp,  g);
    else if (g < SEG1) conv4(w1i, g_w1i, g - SEG0);
    else if (g < SEG2) conv4(w1t, g_w1t, g - SEG1);
    else if (g < SEG3) conv4(w2i, g_w2i, g - SEG2);
    else               conv4(w2t, g_w2t, g - SEG3);
}

// ---------------------------------------------------------------------------
// Fused attention (emits fp16 hid into merged row layout)
// ---------------------------------------------------------------------------
__global__ void __launch_bounds__(256) attn_kernel(
    const float* __restrict__ img, const float* __restrict__ title,
    const int* __restrict__ mask,
    const float* __restrict__ s_img, const float* __restrict__ s_tit)
{
    int blk = blockIdx.x;
    int h   = blk % HH;
    int bl  = blk / HH;

    const float* imgp = img   + (size_t)bl * PP * DD + h * DH;
    const float* titp = title + (size_t)bl * TT * DD + h * DH;
    const int*   mp   = mask  + (size_t)bl * TT;

    __shared__ float sI[PP * DH];
    __shared__ float sT[TT * DH];
    __shared__ float sRaw[PP * TT];
    __shared__ float sPi [PP * TT];
    __shared__ float sPt [TT * PP];
    __shared__ int   sM[TT];

    int tid = threadIdx.x;
    for (int i = tid; i < PP * DH; i += 256) {
        int p = i >> 6, d = i & 63;
        sI[i] = imgp[(size_t)p * DD + d];
    }
    for (int i = tid; i < TT * DH; i += 256) {
        int t = i >> 6, d = i & 63;
        sT[i] = titp[(size_t)t * DD + d];
    }
    if (tid < TT) sM[tid] = mp[tid];
    __syncthreads();

    for (int i = tid; i < PP * TT; i += 256) {
        int p = i / TT, t = i % TT;
        const float* ip = &sI[p * DH];
        const float* tp = &sT[t * DH];
        float acc = 0.f;
        #pragma unroll
        for (int d = 0; d < DH; d++) acc += ip[d] * tp[d];
        sRaw[i] = acc * 0.125f;
    }
    __syncthreads();

    if (tid < PP) {
        int p = tid;
        float sc = s_img[h * PP + p];
        float mx = -1e30f;
        for (int t = 0; t < TT; t++) {
            float x = (sM[t] == 0) ? NEGV : sRaw[p * TT + t] * sc;
            sPi[p * TT + t] = x;
            mx = fmaxf(mx, x);
        }
        float sum = 0.f;
        for (int t = 0; t < TT; t++) {
            float e = __expf(sPi[p * TT + t] - mx);
            sPi[p * TT + t] = e;
            sum += e;
        }
        float inv = 1.f / sum;
        for (int t = 0; t < TT; t++) sPi[p * TT + t] *= inv;
    }
    if (tid >= 64 && tid < 64 + TT) {
        int t = tid - 64;
        float sc = s_tit[h * TT + t];
        bool m0 = (sM[t] == 0);
        float mx = -1e30f;
        for (int p = 0; p < PP; p++) {
            float x = m0 ? NEGV : sRaw[p * TT + t] * sc;
            sPt[t * PP + p] = x;
            mx = fmaxf(mx, x);
        }
        float sum = 0.f;
        for (int p = 0; p < PP; p++) {
            float e = __expf(sPt[t * PP + p] - mx);
            sPt[t * PP + p] = e;
            sum += e;
        }
        float inv = 1.f / sum;
        for (int p = 0; p < PP; p++) sPt[t * PP + p] *= inv;
    }
    __syncthreads();

    for (int i = tid; i < PP * DH; i += 256) {
        int p = i >> 6, d = i & 63;
        float acc = 0.f;
        #pragma unroll
        for (int t = 0; t < TT; t++) acc += sPi[p * TT + t] * sT[t * DH + d];
        size_t idx = ((size_t)(NROW_IMG + bl * PP + p)) * DD + h * DH + d;
        g_hid[idx] = __float2half(acc);
    }
    for (int i = tid; i < TT * DH; i += 256) {
        int t = i >> 6, d = i & 63;
        float acc = 0.f;
        #pragma unroll
        for (int p = 0; p < PP; p++) acc += sPt[t * PP + p] * sI[p * DH + d];
        size_t idx = ((size_t)(bl * TT + t)) * DD + h * DH + d;
        g_hid[idx] = __float2half(acc);
    }
}

// ---------------------------------------------------------------------------
// mma.sync GEMM (fp16, single term): C[M,N] = act(A @ W^T + bias)
// Block tile 64m x 64n, 128 threads / 4 warps (2m x 2n, 32x32 warp tile),
// KC=32, 4-stage cp.async, swizzled smem (8KB/stage) -> 5 CTAs/SM.
// ---------------------------------------------------------------------------
#define KC 32
#define TEN_A 4096u                       // 64 rows x 64B
#define OFF_W TEN_A
#define STG_BYTES (2*TEN_A)               // 8192
#define NSTAGE 4
#define SMEM_GEMM (NSTAGE * STG_BYTES)    // 32768

__device__ __forceinline__ void load_stage(
    uint32_t st,
    const __half* __restrict__ A, const __half* __restrict__ W,
    int m0, int n0, int M, int K, int k0, int tid)
{
    // A: 64 rows x 4 segs = 256 slots; W: same. 128 threads x 2 each.
    #pragma unroll
    for (int i = 0; i < 2; i++) {
        int idx = tid + i * 128;
        int row = idx >> 2, ks = idx & 3;
        uint32_t doff = swaddr((uint32_t)row, (uint32_t)ks);
        int ar = m0 + row;
        int ok = (ar < M);
        size_t ao = (size_t)(ok ? ar : 0) * K + k0 + ks * 8;
        cp16(st + doff,         A + ao, ok ? 16 : 0);
        size_t wo = (size_t)(n0 + row) * K + k0 + ks * 8;
        cp16(st + OFF_W + doff, W + wo, 16);
    }
}

__global__ void __launch_bounds__(128, 5) gemm_mma(
    const __half* __restrict__ A,
    const __half* __restrict__ WA, const __half* __restrict__ WB,
    const float* __restrict__ biasA, const float* __restrict__ biasB,
    float* __restrict__ Cf, __half* __restrict__ Ch,
    int M, int N, int K, int act, int ysplit)
{
    extern __shared__ __align__(128) char smem[];
    uint32_t sb = smem_u32(smem);
    int tid  = threadIdx.x;
    int wid  = tid >> 5, lane = tid & 31;
    int m0   = blockIdx.y * 64;
    int n0   = blockIdx.x * 64;
    int wm   = (wid & 1) * 32;            // 2 m-warps
    int wn   = (wid >> 1) * 32;           // 2 n-warps

    bool regA = ((int)blockIdx.y < ysplit);
    const __half* W    = regA ? WA : WB;
    const float*  bias = regA ? biasA : biasB;

    float acc[2][4][4];
    #pragma unroll
    for (int a = 0; a < 2; a++)
        #pragma unroll
        for (int b = 0; b < 4; b++)
            #pragma unroll
            for (int c = 0; c < 4; c++) acc[a][b][c] = 0.f;

    int nk = K / KC;
    load_stage(sb,                 A, W, m0, n0, M, K, 0,      tid); cp_commit();
    load_stage(sb + STG_BYTES,     A, W, m0, n0, M, K, KC,     tid); cp_commit();
    load_stage(sb + 2 * STG_BYTES, A, W, m0, n0, M, K, 2 * KC, tid); cp_commit();

    uint32_t a_row = (uint32_t)(lane & 15);
    uint32_t a_kof = (uint32_t)((lane >> 4) << 3);
    uint32_t b_r8  = (uint32_t)(lane & 7);
    uint32_t b_kof = (uint32_t)(((lane >> 3) & 1) << 3);
    uint32_t b_pr  = (uint32_t)(lane >> 4);

    for (int it = 0; it < nk; it++) {
        if (it <= nk - 3)      cp_wait2();
        else if (it == nk - 2) cp_wait1();
        else                   cp_wait0();
        __syncthreads();
        if (it + 3 < nk) {
            load_stage(sb + (uint32_t)((it + 3) & 3) * STG_BYTES,
                       A, W, m0, n0, M, K, (it + 3) * KC, tid);
            cp_commit();
        }
        uint32_t st = sb + (uint32_t)(it & 3) * STG_BYTES;

        #pragma unroll
        for (int kk = 0; kk < KC; kk += 16) {
            uint32_t ah[2][4], bf[4][2];
            #pragma unroll
            for (int mt = 0; mt < 2; mt++) {
                uint32_t r = (uint32_t)(wm + mt * 16) + a_row;
                ldsm4(ah[mt], st + swaddr(r, ((uint32_t)kk + a_kof) >> 3));
            }
            #pragma unroll
            for (int np = 0; np < 2; np++) {
                uint32_t rr = (uint32_t)wn + ((uint32_t)np * 2 + b_pr) * 8 + b_r8;
                uint32_t t0[4];
                ldsm4(t0, st + OFF_W + swaddr(rr, ((uint32_t)kk + b_kof) >> 3));
                bf[np*2][0]   = t0[0]; bf[np*2][1]   = t0[1];
                bf[np*2+1][0] = t0[2]; bf[np*2+1][1] = t0[3];
            }
            #pragma unroll
            for (int mt = 0; mt < 2; mt++)
                #pragma unroll
                for (int nt = 0; nt < 4; nt++)
                    mma16816(acc[mt][nt], ah[mt], bf[nt]);
        }
    }

    // epilogue
    int gr = lane >> 2;
    int gc = (lane & 3) * 2;
    #pragma unroll
    for (int mt = 0; mt < 2; mt++) {
        int m_lo = m0 + wm + mt * 16 + gr;
        int m_hi = m_lo + 8;
        #pragma unroll
        for (int nt = 0; nt < 4; nt++) {
            int n = n0 + wn + nt * 8 + gc;
            float2 bv = *(const float2*)&bias[n];
            float v0 = acc[mt][nt][0] + bv.x;
            float v1 = acc[mt][nt][1] + bv.y;
            float v2 = acc[mt][nt][2] + bv.x;
            float v3 = acc[mt][nt][3] + bv.y;
            if (act) { v0 = gelu_fast(v0); v1 = gelu_fast(v1);
                       v2 = gelu_fast(v2); v3 = gelu_fast(v3); }
            if (m_lo < M) {
                size_t o = (size_t)m_lo * N + n;
                if (Cf) *(float2*)&Cf[o] = make_float2(v0, v1);
                if (Ch) {
                    __half2 hp = __floats2half2_rn(v0, v1);
                    *(uint32_t*)&Ch[o] = *(uint32_t*)&hp;
                }
            }
            if (m_hi < M) {
                size_t o = (size_t)m_hi * N + n;
                if (Cf) *(float2*)&Cf[o] = make_float2(v2, v3);
                if (Ch) {
                    __half2 hp = __floats2half2_rn(v2, v3);
                    *(uint32_t*)&Ch[o] = *(uint32_t*)&hp;
                }
            }
        }
    }
}

// ---------------------------------------------------------------------------
// out = R + a * (Y - mean) / (std + eps) + b   per row of 512, ddof=1
// ---------------------------------------------------------------------------
__global__ void __launch_bounds__(128) ln_res_kernel(
    const float* __restrict__ Y, const float* __restrict__ R,
    const float* __restrict__ ga_i, const float* __restrict__ gb_i,
    const float* __restrict__ ga_t, const float* __restrict__ gb_t,
    float* __restrict__ O)
{
    __shared__ float sbuf[4];
    int row = blockIdx.x;
    const float* ga = (row < NROW_IMG) ? ga_i : ga_t;
    const float* gb = (row < NROW_IMG) ? gb_i : gb_t;
    size_t base = (size_t)row * DD;
    int tid = threadIdx.x;

    float x[4];
    #pragma unroll
    for (int i = 0; i < 4; i++) x[i] = Y[base + tid + i * 128];

    float s = x[0] + x[1] + x[2] + x[3];
    #pragma unroll
    for (int o = 16; o > 0; o >>= 1) s += __shfl_xor_sync(0xffffffffu, s, o);
    if ((tid & 31) == 0) sbuf[tid >> 5] = s;
    __syncthreads();
    float mean = (sbuf[0] + sbuf[1] + sbuf[2] + sbuf[3]) * (1.f / 512.f);
    __syncthreads();

    float q = 0.f;
    #pragma unroll
    for (int i = 0; i < 4; i++) { float d = x[i] - mean; q += d * d; }
    #pragma unroll
    for (int o = 16; o > 0; o >>= 1) q += __shfl_xor_sync(0xffffffffu, q, o);
    if ((tid & 31) == 0) sbuf[tid >> 5] = q;
    __syncthreads();
    float var = (sbuf[0] + sbuf[1] + sbuf[2] + sbuf[3]) * (1.f / 511.f);
    float inv = 1.f / (sqrtf(var) + LN_EPS);

    #pragma unroll
    for (int i = 0; i < 4; i++) {
        int n = tid + i * 128;
        O[base + n] = R[base + n] + ga[n] * (x[i] - mean) * inv + gb[n];
    }
}

// ---------------------------------------------------------------------------
extern "C" void kernel_launch(void* const* d_in, const int* in_sizes, int n_in,
                              void* d_out, int out_size)
{
    const float* img         = (const float*)d_in[0];
    const float* title       = (const float*)d_in[1];
    const int*   mask        = (const int*)  d_in[2];
    const float* scale_img   = (const float*)d_in[3];
    const float* scale_title = (const float*)d_in[4];
    const float* w_proj      = (const float*)d_in[5];
    const float* b_proj      = (const float*)d_in[6];
    const float* w1_img      = (const float*)d_in[7];
    const float* b1_img      = (const float*)d_in[8];
    const float* w2_img      = (const float*)d_in[9];
    const float* b2_img      = (const float*)d_in[10];
    const float* w1_tit      = (const float*)d_in[11];
    const float* b1_tit      = (const float*)d_in[12];
    const float* w2_tit      = (const float*)d_in[13];
    const float* b2_tit      = (const float*)d_in[14];
    const float* ln_a_img    = (const float*)d_in[15];
    const float* ln_b_img    = (const float*)d_in[16];
    const float* ln_a_tit    = (const float*)d_in[17];
    const float* ln_b_tit    = (const float*)d_in[18];

    float* out = (float*)d_out;

    cudaFuncSetAttribute(gemm_mma, cudaFuncAttributeMaxDynamicSharedMemorySize, SMEM_GEMM);

    __half *hid, *hidp, *ffh, *wp, *w1i, *w1t, *w2i, *w2t;
    float *hidp_f, *ff2;

    cudaGetSymbolAddress((void**)&hid,    g_hid);
    cudaGetSymbolAddress((void**)&hidp_f, g_hidp_f);
    cudaGetSymbolAddress((void**)&hidp,   g_hidp);
    cudaGetSymbolAddress((void**)&ffh,    g_ffh);
    cudaGetSymbolAddress((void**)&ff2,    g_ff2);
    cudaGetSymbolAddress((void**)&wp,  g_wp);
    cudaGetSymbolAddress((void**)&w1i, g_w1i);
    cudaGetSymbolAddress((void**)&w1t, g_w1t);
    cudaGetSymbolAddress((void**)&w2i, g_w2i);
    cudaGetSymbolAddress((void**)&w2t, g_w2t);

    int ty = (NROW_ALL + 63) / 64;   // 863

    // launch 0: weight convert
    conv_all_kernel<<<(SEG4 / 4 + 255) / 256, 256>>>(w_proj, w1_img, w1_tit, w2_img, w2_tit);

    // launch 1: attention
    attn_kernel<<<BL * HH, 256>>>(img, title, mask, scale_img, scale_title);

    // launch 2: shared projection (f32 residual + fp16 for FFN input)
    gemm_mma<<<dim3(DD/64, ty), 128, SMEM_GEMM>>>(
        hid, wp, wp, b_proj, b_proj,
        hidp_f, hidp, NROW_ALL, DD, DD, 0, ty);

    // launch 3 (ncu capture slot): FFN1 + gelu (fp16 out)
    gemm_mma<<<dim3(DFF/64, ty), 128, SMEM_GEMM>>>(
        hidp, w1i, w1t, b1_img, b1_tit,
        (float*)0, ffh, NROW_ALL, DFF, DD, 1, YT64_IMG);

    // launch 4: FFN2 (f32 out)
    gemm_mma<<<dim3(DD/64, ty), 128, SMEM_GEMM>>>(
        ffh, w2i, w2t, b2_img, b2_tit,
        ff2, (__half*)0, NROW_ALL, DD, DFF, 0, YT64_IMG);

    // launch 5: LayerNorm + residual
    ln_res_kernel<<<NROW_ALL, 128>>>(ff2, hidp_f, ln_a_img, ln_b_img, ln_a_tit, ln_b_tit, out);
}